// round 12
// baseline (speedup 1.0000x reference)
#include <cuda_runtime.h>
#include <cuda_fp16.h>

// Erosion2D: out[b,y,x,c] = min_{dy,dx in [0,4)} x[y+dy-1, x+dx-1, c] - w[3-dy, 3-dx, c]
// fp16x2 compute: smem tile staged as half2 (2 channels/reg), subtraction via __hadd2
// with pre-negated weights, packed __hmin2 mins, 3-deep register ring over columns.
// fp32 in/out. Deltas vs 104.7us baseline: TX 16->32 (halo amp 1.41->1.30, warmup
// 1.19->1.09), launch_bounds (256,5) -> 5 blocks/SM (was capped at 4).

#define BIGF 1e30f

constexpr int B = 8, H = 512, W = 512, C = 32;
constexpr int TY = 16, TX = 32;
constexpr int SR = TY + 3;                 // 19 smem rows
constexpr int SP = TX + 3;                 // 35 smem pixel-columns
constexpr int PIX_H2 = C / 2;              // 16 half2 per pixel
constexpr int SMEM_H2 = SR * SP * PIX_H2;  // 10640 half2 = 42560 B (< 48K static limit)
constexpr int THREADS = 256;

__device__ __forceinline__ unsigned h2u(__half2 h) {
    return reinterpret_cast<unsigned&>(h);
}

__global__ __launch_bounds__(THREADS, 5)
void erosion2d_kernel(const float* __restrict__ xin,
                      const float* __restrict__ wt,
                      float* __restrict__ out) {
    __shared__ __half2 tile[SMEM_H2];

    const int bx = blockIdx.x;          // x tile: 0..15
    const int by = blockIdx.y;          // y tile: 0..31
    const int b  = blockIdx.z;          // batch
    const int x0 = bx * TX;
    const int y0 = by * TY;
    const int tid = threadIdx.x;

    const float* xb = xin + (size_t)b * H * W * C;

    // ---------------- load halo tile into smem (fp32 -> fp16x2) ----------------
    const bool interior = (bx > 0) & (bx < (W / TX - 1)) & (by > 0) & (by < (H / TY - 1));
    constexpr int LOADS = SR * SP * (C / 4);   // float4 loads: 5320

    if (interior) {
        #pragma unroll 4
        for (int i = tid; i < LOADS; i += THREADS) {
            int r   = i / (SP * (C / 4));
            int rem = i - r * (SP * (C / 4));
            int p   = rem >> 3;            // pixel in row (C/4 == 8)
            int q   = rem & 7;             // channel quad
            int gy = y0 - 1 + r;
            int gx = x0 - 1 + p;
            float4 v = *(const float4*)(xb + ((size_t)gy * W + gx) * C + q * 4);
            __half2 h01 = __floats2half2_rn(v.x, v.y);
            __half2 h23 = __floats2half2_rn(v.z, v.w);
            int hi = (r * SP + p) * PIX_H2 + q * 2;
            *(uint2*)(tile + hi) = make_uint2(h2u(h01), h2u(h23));
        }
    } else {
        #pragma unroll 4
        for (int i = tid; i < LOADS; i += THREADS) {
            int r   = i / (SP * (C / 4));
            int rem = i - r * (SP * (C / 4));
            int p   = rem >> 3;
            int q   = rem & 7;
            int gy = y0 - 1 + r;
            int gx = x0 - 1 + p;
            float4 v;
            if (gy >= 0 && gy < H && gx >= 0 && gx < W) {
                v = *(const float4*)(xb + ((size_t)gy * W + gx) * C + q * 4);
            } else {
                v = make_float4(BIGF, BIGF, BIGF, BIGF);   // -> +inf in fp16
            }
            __half2 h01 = __floats2half2_rn(v.x, v.y);
            __half2 h23 = __floats2half2_rn(v.z, v.w);
            int hi = (r * SP + p) * PIX_H2 + q * 2;
            *(uint2*)(tile + hi) = make_uint2(h2u(h01), h2u(h23));
        }
    }

    // ---------------- weights (overlap with staging) ----------------
    const int cp = tid & 15;        // channel pair: channels 2*cp, 2*cp+1
    const int ty = tid >> 4;        // output row in tile: 0..15
    const int c0 = cp * 2;

    // negated reflected weights: nw[d][k] = -w[3-k][3-d][c0..c0+1] as half2
    __half2 nw[4][4];
    #pragma unroll
    for (int d = 0; d < 4; d++) {
        #pragma unroll
        for (int k = 0; k < 4; k++) {
            const float* wp = wt + ((3 - k) * 4 + (3 - d)) * C + c0;
            nw[d][k] = __floats2half2_rn(-wp[0], -wp[1]);
        }
    }

    __syncthreads();

    // ---------------- compute ----------------
    float* op = out + (((size_t)(b * H + y0 + ty) * W + x0) * C) + c0;

    // ring: q0a=c0(s-3) q0b=c0(s-2) q0c=c0(s-1); q1a=c1(s-2) q1b=c1(s-1); q2a=c2(s-1)
    const __half2 BIGH = __floats2half2_rn(BIGF, BIGF);   // +inf pair
    __half2 q0a = BIGH, q0b = BIGH, q0c = BIGH, q1a = BIGH, q1b = BIGH, q2a = BIGH;

    const int rowbase = ty * SP;

    #pragma unroll
    for (int s = 0; s < SP; s++) {
        // 4 input rows of smem column s (this thread's channel pair)
        __half2 r0 = tile[((rowbase) + s) * PIX_H2 + cp];
        __half2 r1 = tile[((rowbase + SP) + s) * PIX_H2 + cp];
        __half2 r2 = tile[((rowbase + 2 * SP) + s) * PIX_H2 + cp];
        __half2 r3 = tile[((rowbase + 3 * SP) + s) * PIX_H2 + cp];

        // column pass: cd[d] = min_k (r_k + nw[d][k])   (packed over 2 channels)
        __half2 cd[4];
        #pragma unroll
        for (int d = 0; d < 4; d++) {
            __half2 a0 = __hadd2(r0, nw[d][0]);
            __half2 a1 = __hadd2(r1, nw[d][1]);
            __half2 a2 = __hadd2(r2, nw[d][2]);
            __half2 a3 = __hadd2(r3, nw[d][3]);
            cd[d] = __hmin2(__hmin2(a0, a1), __hmin2(a2, a3));
        }

        // horizontal combine: out(j=s-3) = min(c0(j), c1(j+1), c2(j+2), c3(j+3))
        if (s >= 3) {
            __half2 o = __hmin2(__hmin2(q0a, q1a), __hmin2(q2a, cd[3]));
            float2 of = __half22float2(o);
            *(float2*)(op + (size_t)(s - 3) * C) = of;
        }

        // shift rings (pure renaming under full unroll)
        q0a = q0b; q0b = q0c; q0c = cd[0];
        q1a = q1b; q1b = cd[1];
        q2a = cd[2];
    }
}

extern "C" void kernel_launch(void* const* d_in, const int* in_sizes, int n_in,
                              void* d_out, int out_size) {
    const float* x = (const float*)d_in[0];
    const float* w = (const float*)d_in[1];
    float* out = (float*)d_out;

    dim3 grid(W / TX, H / TY, B);   // 16 x 32 x 8 = 4096 blocks
    erosion2d_kernel<<<grid, THREADS>>>(x, w, out);
}

// round 14
// speedup vs baseline: 1.0524x; 1.0524x over previous
#include <cuda_runtime.h>
#include <cuda_fp16.h>

// Erosion2D: out[b,y,x,c] = min_{dy,dx in [0,4)} x[y+dy-1, x+dx-1, c] - w[3-dy, 3-dx, c]
// fp16x2 compute: smem tile staged as half2 (2 channels/reg), subtraction via __hadd2
// with pre-negated weights, packed __hmin2 mins, 3-deep register ring over columns.
// fp32 in/out. R13: back to TY=16/TX=16 (23KB smem) + launch_bounds(256,6) to force
// ptxas reg budget <= 42 -> 6 blocks/SM (48 warps, 75% nominal occ).

#define BIGF 1e30f

constexpr int B = 8, H = 512, W = 512, C = 32;
constexpr int TY = 16, TX = 16;
constexpr int SR = TY + 3;                 // 19 smem rows
constexpr int SP = TX + 3;                 // 19 smem pixel-columns
constexpr int PIX_H2 = C / 2;              // 16 half2 per pixel
constexpr int SMEM_H2 = SR * SP * PIX_H2;  // 5776 half2 = 23104 B
constexpr int THREADS = 256;

__device__ __forceinline__ unsigned h2u(__half2 h) {
    return reinterpret_cast<unsigned&>(h);
}

__global__ __launch_bounds__(THREADS, 6)
void erosion2d_kernel(const float* __restrict__ xin,
                      const float* __restrict__ wt,
                      float* __restrict__ out) {
    __shared__ __half2 tile[SMEM_H2];

    const int bx = blockIdx.x;          // x tile: 0..31
    const int by = blockIdx.y;          // y tile: 0..31
    const int b  = blockIdx.z;          // batch
    const int x0 = bx * TX;
    const int y0 = by * TY;
    const int tid = threadIdx.x;

    const float* xb = xin + (size_t)b * H * W * C;

    // ---------------- load halo tile into smem (fp32 -> fp16x2) ----------------
    const bool interior = (bx > 0) & (bx < (W / TX - 1)) & (by > 0) & (by < (H / TY - 1));
    constexpr int LOADS = SR * SP * (C / 4);   // float4 loads: 2888

    if (interior) {
        #pragma unroll 4
        for (int i = tid; i < LOADS; i += THREADS) {
            int r   = i / (SP * (C / 4));
            int rem = i - r * (SP * (C / 4));
            int p   = rem >> 3;            // pixel in row (C/4 == 8)
            int q   = rem & 7;             // channel quad
            int gy = y0 - 1 + r;
            int gx = x0 - 1 + p;
            float4 v = *(const float4*)(xb + ((size_t)gy * W + gx) * C + q * 4);
            __half2 h01 = __floats2half2_rn(v.x, v.y);
            __half2 h23 = __floats2half2_rn(v.z, v.w);
            int hi = (r * SP + p) * PIX_H2 + q * 2;
            *(uint2*)(tile + hi) = make_uint2(h2u(h01), h2u(h23));
        }
    } else {
        #pragma unroll 4
        for (int i = tid; i < LOADS; i += THREADS) {
            int r   = i / (SP * (C / 4));
            int rem = i - r * (SP * (C / 4));
            int p   = rem >> 3;
            int q   = rem & 7;
            int gy = y0 - 1 + r;
            int gx = x0 - 1 + p;
            float4 v;
            if (gy >= 0 && gy < H && gx >= 0 && gx < W) {
                v = *(const float4*)(xb + ((size_t)gy * W + gx) * C + q * 4);
            } else {
                v = make_float4(BIGF, BIGF, BIGF, BIGF);   // -> +inf in fp16
            }
            __half2 h01 = __floats2half2_rn(v.x, v.y);
            __half2 h23 = __floats2half2_rn(v.z, v.w);
            int hi = (r * SP + p) * PIX_H2 + q * 2;
            *(uint2*)(tile + hi) = make_uint2(h2u(h01), h2u(h23));
        }
    }

    // ---------------- weights (overlap with staging) ----------------
    const int cp = tid & 15;        // channel pair: channels 2*cp, 2*cp+1
    const int ty = tid >> 4;        // output row in tile: 0..15
    const int c0 = cp * 2;

    // negated reflected weights: nw[d][k] = -w[3-k][3-d][c0..c0+1] as half2
    __half2 nw[4][4];
    #pragma unroll
    for (int d = 0; d < 4; d++) {
        #pragma unroll
        for (int k = 0; k < 4; k++) {
            const float* wp = wt + ((3 - k) * 4 + (3 - d)) * C + c0;
            nw[d][k] = __floats2half2_rn(-wp[0], -wp[1]);
        }
    }

    __syncthreads();

    // ---------------- compute ----------------
    float* op = out + (((size_t)(b * H + y0 + ty) * W + x0) * C) + c0;

    // ring: q0a=c0(s-3) q0b=c0(s-2) q0c=c0(s-1); q1a=c1(s-2) q1b=c1(s-1); q2a=c2(s-1)
    const __half2 BIGH = __floats2half2_rn(BIGF, BIGF);   // +inf pair
    __half2 q0a = BIGH, q0b = BIGH, q0c = BIGH, q1a = BIGH, q1b = BIGH, q2a = BIGH;

    const int rowbase = ty * SP;

    #pragma unroll
    for (int s = 0; s < SP; s++) {
        // 4 input rows of smem column s (this thread's channel pair)
        __half2 r0 = tile[((rowbase) + s) * PIX_H2 + cp];
        __half2 r1 = tile[((rowbase + SP) + s) * PIX_H2 + cp];
        __half2 r2 = tile[((rowbase + 2 * SP) + s) * PIX_H2 + cp];
        __half2 r3 = tile[((rowbase + 3 * SP) + s) * PIX_H2 + cp];

        // column pass: cd[d] = min_k (r_k + nw[d][k])   (packed over 2 channels)
        __half2 cd[4];
        #pragma unroll
        for (int d = 0; d < 4; d++) {
            __half2 a0 = __hadd2(r0, nw[d][0]);
            __half2 a1 = __hadd2(r1, nw[d][1]);
            __half2 a2 = __hadd2(r2, nw[d][2]);
            __half2 a3 = __hadd2(r3, nw[d][3]);
            cd[d] = __hmin2(__hmin2(a0, a1), __hmin2(a2, a3));
        }

        // horizontal combine: out(j=s-3) = min(c0(j), c1(j+1), c2(j+2), c3(j+3))
        if (s >= 3) {
            __half2 o = __hmin2(__hmin2(q0a, q1a), __hmin2(q2a, cd[3]));
            float2 of = __half22float2(o);
            *(float2*)(op + (size_t)(s - 3) * C) = of;
        }

        // shift rings (pure renaming under full unroll)
        q0a = q0b; q0b = q0c; q0c = cd[0];
        q1a = q1b; q1b = cd[1];
        q2a = cd[2];
    }
}

extern "C" void kernel_launch(void* const* d_in, const int* in_sizes, int n_in,
                              void* d_out, int out_size) {
    const float* x = (const float*)d_in[0];
    const float* w = (const float*)d_in[1];
    float* out = (float*)d_out;

    dim3 grid(W / TX, H / TY, B);   // 32 x 32 x 8 = 8192 blocks
    erosion2d_kernel<<<grid, THREADS>>>(x, w, out);
}